// round 2
// baseline (speedup 1.0000x reference)
#include <cuda_runtime.h>
#include <cuda_bf16.h>

// CoordsToNRF: out[b,p] = atoms_flat[p] * (AU2KCALMOLA / MAX_NRF) / |c[b,i]-c[b,j]|^2
// where (i,j) is the p-th strict-lower-triangle pair (row-major, i ascending, j<i).
// B=2048, N=128, NC2=8128. Store-bound: 66.6 MB output.

#define N_ATOMS 128
#define NC2     8128          // 128*127/2
#define NVEC    (NC2 / 4)     // 2032 float4 per row
#define BATCH   2048

__global__ __launch_bounds__(256) void coords_to_nrf_kernel(
    const float* __restrict__ coords,   // [B, N, 3]
    const float* __restrict__ atoms,    // [NC2]
    float* __restrict__ out)            // [B, NC2]
{
    __shared__ float sx[N_ATOMS];
    __shared__ float sy[N_ATOMS];
    __shared__ float sz[N_ATOMS];

    const int b = blockIdx.x;
    const float* c = coords + (size_t)b * N_ATOMS * 3;

    // Stage this molecule's coords into SMEM (SoA to keep LDS conflict-free).
    for (int a = threadIdx.x; a < N_ATOMS; a += blockDim.x) {
        sx[a] = c[3 * a + 0];
        sy[a] = c[3 * a + 1];
        sz[a] = c[3 * a + 2];
    }
    __syncthreads();

    const float SCALE = 627.5095f * 0.529177f / 100.0f;  // AU2KCALMOLA / MAX_NRF

    float* orow = out + (size_t)b * NC2;
    const float4* atoms4 = reinterpret_cast<const float4*>(atoms);
    float4* out4 = reinterpret_cast<float4*>(orow);

    // Grid-stride over float4 vectors of the row: coalesced STG.128.
    for (int v = threadIdx.x; v < NVEC; v += blockDim.x) {
        const int p0 = v * 4;

        // Triangular inverse: largest i with i*(i-1)/2 <= p0.
        int i = (int)((1.0f + sqrtf(1.0f + 8.0f * (float)p0)) * 0.5f);
        while (i * (i - 1) / 2 > p0) --i;          // fixup (at most 1 step)
        while ((i + 1) * i / 2 <= p0) ++i;

        int j = p0 - i * (i - 1) / 2;

        float4 a4 = __ldg(&atoms4[v]);
        const float* aa = reinterpret_cast<const float*>(&a4);

        float xi = sx[i], yi = sy[i], zi = sz[i];
        float res[4];

        #pragma unroll
        for (int k = 0; k < 4; ++k) {
            if (j >= i) {                  // row boundary: advance i, restart j
                ++i;
                j = 0;
                xi = sx[i]; yi = sy[i]; zi = sz[i];
            }
            float dx = xi - sx[j];
            float dy = yi - sy[j];
            float dz = zi - sz[j];
            float r2 = fmaf(dx, dx, fmaf(dy, dy, dz * dz));
            res[k] = aa[k] * (SCALE / r2);
            ++j;
        }

        out4[v] = make_float4(res[0], res[1], res[2], res[3]);
    }
}

extern "C" void kernel_launch(void* const* d_in, const int* in_sizes, int n_in,
                              void* d_out, int out_size)
{
    // Resolve inputs by size: coords has 2048*128*3 = 786432 elems, atoms 8128.
    const float* coords = (const float*)d_in[0];
    const float* atoms  = (const float*)d_in[1];
    if (n_in >= 2 && in_sizes[0] == NC2) {  // order swapped
        atoms  = (const float*)d_in[0];
        coords = (const float*)d_in[1];
    }
    float* out = (float*)d_out;

    coords_to_nrf_kernel<<<BATCH, 256>>>(coords, atoms, out);
}

// round 5
// speedup vs baseline: 1.0651x; 1.0651x over previous
#include <cuda_runtime.h>
#include <cuda_bf16.h>

// CoordsToNRF: out[b,p] = atoms[p] * (AU2KCALMOLA/MAX_NRF) / |c[b,i]-c[b,j]|^2
// p-th strict-lower-triangle pair (row-major). B=2048, N=128, NC2=8128.
// Output (66.6MB) fits in L2 -> kernel is L1/issue bound, not DRAM bound.
// Key tricks: 4 shifted SMEM copies make stride-4 float4 j-loads conflict-free;
// packed float4 i-coords; fast reciprocal instead of full FDIV.

#define N_ATOMS 128
#define NC2     8128
#define NVEC    2032          // NC2 / 4
#define BATCH   2048

__global__ __launch_bounds__(256) void coords_to_nrf_kernel(
    const float* __restrict__ coords,   // [B, N, 3]
    const float* __restrict__ atoms,    // [NC2]
    float* __restrict__ out)            // [B, NC2]
{
    __shared__ __align__(16) float4 sxyz[N_ATOMS];      // packed (x,y,z,0)
    __shared__ __align__(16) float shx[4][N_ATOMS];     // shx[r][e] = x[e+r]
    __shared__ __align__(16) float shy[4][N_ATOMS];
    __shared__ __align__(16) float shz[4][N_ATOMS];

    const int b = blockIdx.x;
    const float* c = coords + (size_t)b * N_ATOMS * 3;

    for (int a = threadIdx.x; a < N_ATOMS; a += 256) {
        float x = c[3 * a + 0];
        float y = c[3 * a + 1];
        float z = c[3 * a + 2];
        sxyz[a] = make_float4(x, y, z, 0.f);
    }
    __syncthreads();

    // Build 4 shifted copies: copy r, element e holds atom (e+r).
    for (int idx = threadIdx.x; idx < 4 * N_ATOMS; idx += 256) {
        int r = idx >> 7;
        int e = idx & 127;
        int s = e + r;
        float4 v = (s < N_ATOMS) ? sxyz[s] : make_float4(0.f, 0.f, 0.f, 0.f);
        shx[r][e] = v.x;
        shy[r][e] = v.y;
        shz[r][e] = v.z;
    }
    __syncthreads();

    const float SCALE = 627.5095f * 0.529177f / 100.0f;

    const float4* __restrict__ atoms4 = reinterpret_cast<const float4*>(atoms);
    float4* __restrict__ out4 = reinterpret_cast<float4*>(out + (size_t)b * NC2);

    for (int v = threadIdx.x; v < NVEC; v += 256) {
        const int p0 = v * 4;

        // Triangular inverse: largest i with i*(i-1)/2 <= p0.
        int i = (int)((1.0f + sqrtf((float)(8 * p0 + 1))) * 0.5f);
        while (i * (i - 1) / 2 > p0) --i;
        while ((i + 1) * i / 2 <= p0) ++i;
        int j = p0 - i * (i - 1) / 2;

        float4 a4 = __ldg(&atoms4[v]);
        float4 res;

        if (j + 4 <= i) {
            // Fast path: all 4 pairs in row i, j..j+3 consecutive.
            float4 ci = sxyz[i];                       // broadcast LDS.128
            int r = j & 3;
            int e = j & ~3;
            float4 xj = *reinterpret_cast<const float4*>(&shx[r][e]);
            float4 yj = *reinterpret_cast<const float4*>(&shy[r][e]);
            float4 zj = *reinterpret_cast<const float4*>(&shz[r][e]);

            float dx, dy, dz, r2;
            dx = ci.x - xj.x; dy = ci.y - yj.x; dz = ci.z - zj.x;
            r2 = fmaf(dx, dx, fmaf(dy, dy, dz * dz));
            res.x = __fdividef(a4.x * SCALE, r2);

            dx = ci.x - xj.y; dy = ci.y - yj.y; dz = ci.z - zj.y;
            r2 = fmaf(dx, dx, fmaf(dy, dy, dz * dz));
            res.y = __fdividef(a4.y * SCALE, r2);

            dx = ci.x - xj.z; dy = ci.y - yj.z; dz = ci.z - zj.z;
            r2 = fmaf(dx, dx, fmaf(dy, dy, dz * dz));
            res.z = __fdividef(a4.z * SCALE, r2);

            dx = ci.x - xj.w; dy = ci.y - yj.w; dz = ci.z - zj.w;
            r2 = fmaf(dx, dx, fmaf(dy, dy, dz * dz));
            res.w = __fdividef(a4.w * SCALE, r2);
        } else {
            // Slow path: vector crosses a row boundary (~6% of vectors).
            float4 ci = sxyz[i];
            float rr[4];
            const float* aa = reinterpret_cast<const float*>(&a4);
            #pragma unroll
            for (int k = 0; k < 4; ++k) {
                if (j >= i) { ++i; j = 0; ci = sxyz[i]; }
                float4 cj = sxyz[j];
                float dx = ci.x - cj.x;
                float dy = ci.y - cj.y;
                float dz = ci.z - cj.z;
                float r2 = fmaf(dx, dx, fmaf(dy, dy, dz * dz));
                rr[k] = __fdividef(aa[k] * SCALE, r2);
                ++j;
            }
            res = make_float4(rr[0], rr[1], rr[2], rr[3]);
        }

        out4[v] = res;
    }
}

extern "C" void kernel_launch(void* const* d_in, const int* in_sizes, int n_in,
                              void* d_out, int out_size)
{
    const float* coords = (const float*)d_in[0];
    const float* atoms  = (const float*)d_in[1];
    if (n_in >= 2 && in_sizes[0] == NC2) {  // order swapped
        atoms  = (const float*)d_in[0];
        coords = (const float*)d_in[1];
    }
    float* out = (float*)d_out;

    coords_to_nrf_kernel<<<BATCH, 256>>>(coords, atoms, out);
}

// round 7
// speedup vs baseline: 1.1405x; 1.0708x over previous
#include <cuda_runtime.h>
#include <cuda_bf16.h>

// CoordsToNRF: out[b, p(i,j)] = atoms[p] * (AU2KCALMOLA/MAX_NRF) / |c[b,i]-c[b,j]|^2
// B=2048, N=128, NC2=8128. Output fits in L2 -> kernel was issue/ALU bound.
// Row-parallel scheme: warp w handles rows i = w+1, w+9, ... Each lane preloads
// coords of atoms {lane, 32+lane, 64+lane, 96+lane} into registers; pass k of any
// row needs exactly rx[k] per lane (j == lane mod 32). Zero SMEM, zero triangular
// inverse, no per-pair index math. Row (xi,yi,zi) comes from 3 shuffles per row.

#define N_ATOMS 128
#define NC2     8128
#define BATCH   2048

__global__ __launch_bounds__(256) void coords_to_nrf_kernel(
    const float* __restrict__ coords,   // [B, N, 3]
    const float* __restrict__ atoms,    // [NC2]
    float* __restrict__ out)            // [B, NC2]
{
    const int b    = blockIdx.x;
    const int lane = threadIdx.x & 31;
    const int w    = threadIdx.x >> 5;

    const float* __restrict__ c = coords + (size_t)b * (N_ATOMS * 3);

    // Register-resident coords: rx[k] = x[32k + lane], etc.
    float rx[4], ry[4], rz[4];
#pragma unroll
    for (int k = 0; k < 4; ++k) {
        const int a = (k << 5) + lane;
        rx[k] = c[3 * a + 0];
        ry[k] = c[3 * a + 1];
        rz[k] = c[3 * a + 2];
    }

    const float SCALE = 627.5095f * 0.529177f / 100.0f;  // AU2KCALMOLA / MAX_NRF
    float* __restrict__ orow = out + (size_t)b * NC2;

    // Warp w processes rows w+1, w+9, ..., interleaved for load balance.
    for (int i = w + 1; i < N_ATOMS; i += 8) {
        // Broadcast atom i's coords: select static register by ki, shuffle lane li.
        const int ki = i >> 5;
        const int li = i & 31;
        float sxk = (ki == 0) ? rx[0] : (ki == 1) ? rx[1] : (ki == 2) ? rx[2] : rx[3];
        float syk = (ki == 0) ? ry[0] : (ki == 1) ? ry[1] : (ki == 2) ? ry[2] : ry[3];
        float szk = (ki == 0) ? rz[0] : (ki == 1) ? rz[1] : (ki == 2) ? rz[2] : rz[3];
        const float xi = __shfl_sync(0xffffffffu, sxk, li);
        const float yi = __shfl_sync(0xffffffffu, syk, li);
        const float zi = __shfl_sync(0xffffffffu, szk, li);

        const int base = (i * (i - 1)) >> 1;
        const int kmax = (i + 31) >> 5;     // number of 32-wide passes in this row

        // GUARD is an expression in j and i. Loads are index-clamped (row 127's
        // last pass would otherwise read atoms[8128], one past the end).
#define NRF_PASS(k, FULL)                                                        \
        {                                                                        \
            const int j   = ((k) << 5) + lane;                                   \
            const int p   = base + j;                                            \
            const float dx = xi - rx[k];                                         \
            const float dy = yi - ry[k];                                         \
            const float dz = zi - rz[k];                                         \
            const float r2 = fmaf(dx, dx, fmaf(dy, dy, dz * dz));                \
            const int   pl = (FULL) ? p : (p < NC2 ? p : NC2 - 1);               \
            const float vv = __fdividef(__ldg(&atoms[pl]) * SCALE, r2);          \
            if ((FULL) || (j < i)) orow[p] = vv;                                 \
        }

        switch (kmax) {
            case 1:  NRF_PASS(0, false); break;
            case 2:  NRF_PASS(0, true);  NRF_PASS(1, false); break;
            case 3:  NRF_PASS(0, true);  NRF_PASS(1, true);  NRF_PASS(2, false); break;
            default: NRF_PASS(0, true);  NRF_PASS(1, true);  NRF_PASS(2, true);
                     NRF_PASS(3, false); break;
        }
#undef NRF_PASS
    }
}

extern "C" void kernel_launch(void* const* d_in, const int* in_sizes, int n_in,
                              void* d_out, int out_size)
{
    const float* coords = (const float*)d_in[0];
    const float* atoms  = (const float*)d_in[1];
    if (n_in >= 2 && in_sizes[0] == NC2) {  // order swapped
        atoms  = (const float*)d_in[0];
        coords = (const float*)d_in[1];
    }
    float* out = (float*)d_out;

    coords_to_nrf_kernel<<<BATCH, 256>>>(coords, atoms, out);
}